// round 5
// baseline (speedup 1.0000x reference)
#include <cuda_runtime.h>
#include <cstdint>

// VQ nearest-codebook, fp32-exact, Blackwell dual-FP32 (fma.rn.f32x2).
// Tile: thread = 16 points x 4 codewords; warp = 16 points x 128 codewords.
// Block = 128 points (2 (b,h) rows), 256 threads, grid 512.

#define DD 64
#define KTOT 1024
#define TK 128          // codewords per chunk
#define TMB 128         // points per block
#define NTHREADS 256

#define PSROW 264       // 128 dup-pairs = 256 floats + 8 pad (16B-aligned rows)
#define CSROW 132       // 128 floats + 4 pad
#define SMEM_FLOATS (DD * PSROW + DD * CSROW)   // 25344 floats = 101376 B

__device__ float g_cbT[DD * KTOT];   // codebook transposed [d][k]
__device__ float g_cnorm[KTOT];

#define FMA2(d, a, b) \
    asm("fma.rn.f32x2 %0, %1, %2, %0;" : "+l"(d) : "l"(a), "l"(b))
#define UNPACK2(u0, u1, v) \
    asm("mov.b64 {%0, %1}, %2;" : "=r"(u0), "=r"(u1) : "l"(v))

// ---------------- prep: transpose codebook + norms --------------------------
__global__ void __launch_bounds__(NTHREADS)
prep_cb(const float* __restrict__ cb) {
    int k = blockIdx.x * blockDim.x + threadIdx.x;
    if (k >= KTOT) return;
    float s = 0.f;
#pragma unroll
    for (int d4 = 0; d4 < DD; d4 += 4) {
        float4 v = *(const float4*)(cb + (size_t)k * DD + d4);
        s += v.x * v.x + v.y * v.y + v.z * v.z + v.w * v.w;
        g_cbT[(d4 + 0) * KTOT + k] = v.x;
        g_cbT[(d4 + 1) * KTOT + k] = v.y;
        g_cbT[(d4 + 2) * KTOT + k] = v.z;
        g_cbT[(d4 + 3) * KTOT + k] = v.w;
    }
    g_cnorm[k] = s;
}

// ---------------- main fused kernel -----------------------------------------
__global__ void __launch_bounds__(NTHREADS, 2)
vq_kernel(const float* __restrict__ x, const float* __restrict__ cb,
          float* __restrict__ out, int write_idx) {
    extern __shared__ float smem[];
    float* psd = smem;                 // [DD][PSROW] duplicated points (a,a)
    float* cs  = smem + DD * PSROW;    // [DD][CSROW] codeword chunk

    const int tid = threadIdx.x;
    const int wid = tid >> 5;          // warp -> points 16*wid .. 16*wid+15
    const int tx  = tid & 31;          // lane -> codewords 4*tx .. 4*tx+3

    const int bh0 = blockIdx.x * 2;    // two (b,h) rows per block
    const int b = bh0 >> 6;
    const int h0 = bh0 & 63;
    // x[b][d][h][w]
    const float* xbase = x + (size_t)b * (DD * 4096) + (size_t)h0 * 64;

    // Load + duplicate: psd[d][2p], psd[d][2p+1] = x[..][d][h0 + p/64][p%64]
    for (int i = tid; i < DD * 32; i += NTHREADS) {
        int d  = i >> 5;
        int p4 = (i & 31) * 4;                 // points p4..p4+3
        int r  = p4 >> 6;                      // 0 or 1 (which h row)
        int w  = p4 & 63;
        float4 v = *(const float4*)(xbase + (size_t)d * 4096 + r * 64 + w);
        float* row = psd + d * PSROW + 2 * p4;
        *(float4*)(row + 0) = make_float4(v.x, v.x, v.y, v.y);
        *(float4*)(row + 4) = make_float4(v.z, v.z, v.w, v.w);
    }

    float bestv[16];
    int   besti[16];
#pragma unroll
    for (int p = 0; p < 16; p++) { bestv[p] = 3.4e38f; besti[p] = 0; }

    const float* arow0 = psd + 32 * wid;   // this warp's 16 dup-pairs = 128 B
    const float* brow0 = cs + 4 * tx;

    for (int chunk = 0; chunk < KTOT; chunk += TK) {
        __syncthreads();  // previous iteration done reading cs
        for (int i = tid; i < DD * 32; i += NTHREADS) {
            int d  = i >> 5;
            int c4 = (i & 31) * 4;
            *(float4*)(cs + d * CSROW + c4) =
                *(const float4*)(g_cbT + (size_t)d * KTOT + chunk + c4);
        }
        __syncthreads();

        // acc[p][q]: point p (16), codeword-pair q (2) -> 4 codewords
        unsigned long long acc[16][2];
#pragma unroll
        for (int p = 0; p < 16; p++) { acc[p][0] = 0ull; acc[p][1] = 0ull; }

#pragma unroll 2
        for (int d = 0; d < DD; d++) {
            const ulonglong2* ar = (const ulonglong2*)(arow0 + (size_t)d * PSROW);
            ulonglong2 bb = *(const ulonglong2*)(brow0 + (size_t)d * CSROW);
#pragma unroll
            for (int q = 0; q < 8; q++) {      // 8 x ulonglong2 = 16 dup pairs
                ulonglong2 a = ar[q];
                FMA2(acc[2 * q + 0][0], a.x, bb.x);
                FMA2(acc[2 * q + 0][1], a.x, bb.y);
                FMA2(acc[2 * q + 1][0], a.y, bb.x);
                FMA2(acc[2 * q + 1][1], a.y, bb.y);
            }
        }

        // d2 = ||c||^2 - 2 x.c ; ascending c + strict < = first-idx tie-break.
        const int c0 = chunk + 4 * tx;
        float4 nrm = __ldg((const float4*)(g_cnorm + c0));
#pragma unroll
        for (int p = 0; p < 16; p++) {
            uint32_t u0, u1, u2, u3;
            UNPACK2(u0, u1, acc[p][0]);
            UNPACK2(u2, u3, acc[p][1]);
            float d2;
            d2 = fmaf(-2.f, __uint_as_float(u0), nrm.x);
            if (d2 < bestv[p]) { bestv[p] = d2; besti[p] = c0 + 0; }
            d2 = fmaf(-2.f, __uint_as_float(u1), nrm.y);
            if (d2 < bestv[p]) { bestv[p] = d2; besti[p] = c0 + 1; }
            d2 = fmaf(-2.f, __uint_as_float(u2), nrm.z);
            if (d2 < bestv[p]) { bestv[p] = d2; besti[p] = c0 + 2; }
            d2 = fmaf(-2.f, __uint_as_float(u3), nrm.w);
            if (d2 < bestv[p]) { bestv[p] = d2; besti[p] = c0 + 3; }
        }
    }

    // Warp-level argmin across 32 lanes (disjoint codeword ranges).
#pragma unroll
    for (int off = 16; off > 0; off >>= 1) {
#pragma unroll
        for (int p = 0; p < 16; p++) {
            float v2 = __shfl_down_sync(0xFFFFFFFFu, bestv[p], off);
            int   c2 = __shfl_down_sync(0xFFFFFFFFu, besti[p], off);
            if (v2 < bestv[p] || (v2 == bestv[p] && c2 < besti[p])) {
                bestv[p] = v2;
                besti[p] = c2;
            }
        }
    }

    __syncthreads();  // all done with psd/cs before smem reuse
    int* bidx = (int*)smem;  // 128 ints
    if (tx == 0) {
#pragma unroll
        for (int p = 0; p < 16; p++) bidx[16 * wid + p] = besti[p];
    }
    __syncthreads();

    // Gather winning codebook rows coalesced into smem, then write transposed.
    float* tmp = smem + 256;  // [TMB][68] staging
    for (int i = tid; i < TMB * 16; i += NTHREADS) {
        int p  = i >> 4;
        int d4 = (i & 15) * 4;
        *(float4*)(tmp + p * 68 + d4) =
            *(const float4*)(cb + (size_t)bidx[p] * DD + d4);
    }
    __syncthreads();
    float* qbase = out + (size_t)b * (DD * 4096) + (size_t)h0 * 64;
    for (int i = tid; i < DD * 32; i += NTHREADS) {
        int d  = i >> 5;
        int p4 = (i & 31) * 4;
        int r  = p4 >> 6;
        int w  = p4 & 63;
        float4 v;
        v.x = tmp[(p4 + 0) * 68 + d];
        v.y = tmp[(p4 + 1) * 68 + d];
        v.z = tmp[(p4 + 2) * 68 + d];
        v.w = tmp[(p4 + 3) * 68 + d];
        *(float4*)(qbase + (size_t)d * 4096 + r * 64 + w) = v;
    }

    if (write_idx && tid < TMB) {
        out[(size_t)4194304 + (size_t)bh0 * 64 + tid] = (float)bidx[tid];
    }
}

// ---------------- launch -----------------------------------------------------
extern "C" void kernel_launch(void* const* d_in, const int* in_sizes, int n_in,
                              void* d_out, int out_size) {
    const float* x  = (const float*)d_in[0];
    const float* cb = (const float*)d_in[1];
    if (n_in >= 2 && in_sizes[0] == KTOT * DD && in_sizes[1] == 16 * 64 * 64 * 64) {
        x  = (const float*)d_in[1];
        cb = (const float*)d_in[0];
    }
    float* out = (float*)d_out;

    const int smem_bytes = SMEM_FLOATS * (int)sizeof(float);
    cudaFuncSetAttribute(vq_kernel, cudaFuncAttributeMaxDynamicSharedMemorySize,
                         smem_bytes);

    int write_idx = (out_size >= 4194304 + 65536) ? 1 : 0;
    prep_cb<<<(KTOT + NTHREADS - 1) / NTHREADS, NTHREADS>>>(cb);
    vq_kernel<<<512, NTHREADS, smem_bytes>>>(x, cb, out, write_idx);
}

// round 8
// speedup vs baseline: 1.5835x; 1.5835x over previous
#include <cuda_runtime.h>
#include <cstdint>

// VQ nearest-codebook, fp32-exact, Blackwell dual-FP32 (fma.rn.f32x2).
// f32x2 lanes carry a POINT PAIR; the codeword is duplicated in registers.
// Thread tile: 8 points x 4 codewords. Block = 64 points (one (b,h) row).
// (Resubmission after two broker-side container failures; source semantics
// identical to the round-6/7 candidate.)

#define DD 64
#define KTOT 1024
#define TK 128          // codewords per chunk
#define TM 64           // points per block
#define NTHREADS 256

#define PSROW 68        // 64 points + 4 pad (16B-aligned rows)
#define CSROW 132       // 128 codewords + 4 pad
#define SMEM_FLOATS (DD * PSROW + DD * CSROW)   // 12800 floats = 51200 B

__device__ float g_cbT[DD * KTOT];   // codebook transposed [d][k]
__device__ float g_cnorm[KTOT];

#define FMA2(d, a, b) \
    asm("fma.rn.f32x2 %0, %1, %2, %0;" : "+l"(d) : "l"(a), "l"(b))
#define UNPACK2(u0, u1, v) \
    asm("mov.b64 {%0, %1}, %2;" : "=r"(u0), "=r"(u1) : "l"(v))
#define DUP2(d, s) \
    asm("mov.b64 %0, {%1, %1};" : "=l"(d) : "r"(s))

// ---------------- prep: transpose codebook + norms --------------------------
__global__ void __launch_bounds__(NTHREADS)
prep_cb(const float* __restrict__ cb) {
    int k = blockIdx.x * blockDim.x + threadIdx.x;
    if (k >= KTOT) return;
    float s = 0.f;
#pragma unroll
    for (int d4 = 0; d4 < DD; d4 += 4) {
        float4 v = *(const float4*)(cb + (size_t)k * DD + d4);
        s += v.x * v.x + v.y * v.y + v.z * v.z + v.w * v.w;
        g_cbT[(d4 + 0) * KTOT + k] = v.x;
        g_cbT[(d4 + 1) * KTOT + k] = v.y;
        g_cbT[(d4 + 2) * KTOT + k] = v.z;
        g_cbT[(d4 + 3) * KTOT + k] = v.w;
    }
    g_cnorm[k] = s;
}

// ---------------- main fused kernel -----------------------------------------
__global__ void __launch_bounds__(NTHREADS, 2)
vq_kernel(const float* __restrict__ x, const float* __restrict__ cb,
          float* __restrict__ out, int write_idx) {
    extern __shared__ float smem[];
    float* ps = smem;                  // [DD][PSROW]  ps[d][w] = x[b][d][h][w]
    float* cs = smem + DD * PSROW;     // [DD][CSROW]  chunk of transposed cb

    const int tid = threadIdx.x;
    const int wid = tid >> 5;          // warp -> points 8*wid .. 8*wid+7
    const int tx  = tid & 31;          // lane -> codewords 4*tx .. 4*tx+3

    const int bh = blockIdx.x;         // 0..1023
    const int b = bh >> 6;
    const int h = bh & 63;
    const float* xbase = x + (size_t)b * (DD * 4096) + (size_t)h * 64;

    // Point tile: straight float4 copy, natural layout (w contiguous both sides).
    for (int i = tid; i < DD * 16; i += NTHREADS) {
        int d  = i >> 4;
        int w4 = (i & 15) * 4;
        *(float4*)(ps + d * PSROW + w4) =
            *(const float4*)(xbase + (size_t)d * 4096 + w4);
    }

    float bestv[8];
    int   besti[8];
#pragma unroll
    for (int p = 0; p < 8; p++) { bestv[p] = 3.4e38f; besti[p] = 0; }

    const float* arow0 = ps + 8 * wid;     // warp's 8 points (32 B, 16B-aligned)
    const float* brow0 = cs + 4 * tx;

    for (int chunk = 0; chunk < KTOT; chunk += TK) {
        __syncthreads();  // previous iteration done reading cs
        for (int i = tid; i < DD * 32; i += NTHREADS) {
            int d  = i >> 5;
            int c4 = (i & 31) * 4;
            *(float4*)(cs + d * CSROW + c4) =
                *(const float4*)(g_cbT + (size_t)d * KTOT + chunk + c4);
        }
        __syncthreads();

        // acc[q][j]: lanes = (point 2q, point 2q+1), codeword j of this lane.
        unsigned long long acc[4][4];
#pragma unroll
        for (int q = 0; q < 4; q++)
#pragma unroll
            for (int j = 0; j < 4; j++) acc[q][j] = 0ull;

#pragma unroll 4
        for (int d = 0; d < DD; d++) {
            // a: warp's 8 points at this d -> 4 natural pairs (2 broadcast LDS.128)
            const ulonglong2* ar = (const ulonglong2*)(arow0 + (size_t)d * PSROW);
            ulonglong2 arv0 = ar[0];   // pairs (p0,p1), (p2,p3)
            ulonglong2 arv1 = ar[1];   // pairs (p4,p5), (p6,p7)
            // b: this lane's 4 codewords at d (1 distributed LDS.128), dup in regs
            float4 c = *(const float4*)(brow0 + (size_t)d * CSROW);
            unsigned long long b0, b1, b2, b3;
            DUP2(b0, __float_as_uint(c.x));
            DUP2(b1, __float_as_uint(c.y));
            DUP2(b2, __float_as_uint(c.z));
            DUP2(b3, __float_as_uint(c.w));
            FMA2(acc[0][0], arv0.x, b0); FMA2(acc[0][1], arv0.x, b1);
            FMA2(acc[0][2], arv0.x, b2); FMA2(acc[0][3], arv0.x, b3);
            FMA2(acc[1][0], arv0.y, b0); FMA2(acc[1][1], arv0.y, b1);
            FMA2(acc[1][2], arv0.y, b2); FMA2(acc[1][3], arv0.y, b3);
            FMA2(acc[2][0], arv1.x, b0); FMA2(acc[2][1], arv1.x, b1);
            FMA2(acc[2][2], arv1.x, b2); FMA2(acc[2][3], arv1.x, b3);
            FMA2(acc[3][0], arv1.y, b0); FMA2(acc[3][1], arv1.y, b1);
            FMA2(acc[3][2], arv1.y, b2); FMA2(acc[3][3], arv1.y, b3);
        }

        // d2 = ||c||^2 - 2 x.c ; ascending codeword order + strict < ==
        // first-index tie-break (matches jnp.argmin).
        const int c0 = chunk + 4 * tx;
        float4 nrm = __ldg((const float4*)(g_cnorm + c0));
        const float nn[4] = {nrm.x, nrm.y, nrm.z, nrm.w};
#pragma unroll
        for (int j = 0; j < 4; j++) {
#pragma unroll
            for (int q = 0; q < 4; q++) {
                uint32_t u0, u1;
                UNPACK2(u0, u1, acc[q][j]);
                float d2a = fmaf(-2.f, __uint_as_float(u0), nn[j]);
                float d2b = fmaf(-2.f, __uint_as_float(u1), nn[j]);
                if (d2a < bestv[2 * q + 0]) { bestv[2 * q + 0] = d2a; besti[2 * q + 0] = c0 + j; }
                if (d2b < bestv[2 * q + 1]) { bestv[2 * q + 1] = d2b; besti[2 * q + 1] = c0 + j; }
            }
        }
    }

    // Warp argmin across lanes (disjoint codeword ranges, same 8 points).
#pragma unroll
    for (int off = 16; off > 0; off >>= 1) {
#pragma unroll
        for (int p = 0; p < 8; p++) {
            float v2 = __shfl_down_sync(0xFFFFFFFFu, bestv[p], off);
            int   c2 = __shfl_down_sync(0xFFFFFFFFu, besti[p], off);
            if (v2 < bestv[p] || (v2 == bestv[p] && c2 < besti[p])) {
                bestv[p] = v2;
                besti[p] = c2;
            }
        }
    }

    __syncthreads();  // all done with ps/cs before smem reuse
    int* bidx = (int*)smem;  // 64 ints
    if (tx == 0) {
#pragma unroll
        for (int p = 0; p < 8; p++) bidx[8 * wid + p] = besti[p];
    }
    __syncthreads();

    // Gather winning codebook rows coalesced into smem, then write transposed.
    float* tmp = smem + 128;  // [TM][68] staging
    for (int i = tid; i < TM * 16; i += NTHREADS) {
        int w  = i >> 4;
        int d4 = (i & 15) * 4;
        *(float4*)(tmp + w * 68 + d4) =
            *(const float4*)(cb + (size_t)bidx[w] * DD + d4);
    }
    __syncthreads();
    float* qbase = out + (size_t)b * (DD * 4096) + (size_t)h * 64;
    for (int i = tid; i < TM * 16; i += NTHREADS) {
        int d  = i >> 4;
        int w4 = (i & 15) * 4;
        float4 v;
        v.x = tmp[(w4 + 0) * 68 + d];
        v.y = tmp[(w4 + 1) * 68 + d];
        v.z = tmp[(w4 + 2) * 68 + d];
        v.w = tmp[(w4 + 3) * 68 + d];
        *(float4*)(qbase + (size_t)d * 4096 + w4) = v;
    }

    if (write_idx && tid < TM) {
        out[(size_t)4194304 + (size_t)bh * 64 + tid] = (float)bidx[tid];
    }
}

// ---------------- launch -----------------------------------------------------
extern "C" void kernel_launch(void* const* d_in, const int* in_sizes, int n_in,
                              void* d_out, int out_size) {
    const float* x  = (const float*)d_in[0];
    const float* cb = (const float*)d_in[1];
    if (n_in >= 2 && in_sizes[0] == KTOT * DD && in_sizes[1] == 16 * 64 * 64 * 64) {
        x  = (const float*)d_in[1];
        cb = (const float*)d_in[0];
    }
    float* out = (float*)d_out;

    const int smem_bytes = SMEM_FLOATS * (int)sizeof(float);
    cudaFuncSetAttribute(vq_kernel, cudaFuncAttributeMaxDynamicSharedMemorySize,
                         smem_bytes);

    int write_idx = (out_size >= 4194304 + 65536) ? 1 : 0;
    prep_cb<<<(KTOT + NTHREADS - 1) / NTHREADS, NTHREADS>>>(cb);
    vq_kernel<<<1024, NTHREADS, smem_bytes>>>(x, cb, out, write_idx);
}

// round 9
// speedup vs baseline: 1.6307x; 1.0298x over previous
#include <cuda_runtime.h>
#include <cstdint>

// VQ nearest-codebook, fp32-exact, Blackwell dual-FP32 (fma.rn.f32x2),
// cp.async double-buffered codebook chunks.
// f32x2 lanes carry a POINT PAIR; codeword duplicated in registers.
// Thread tile: 8 points x 4 codewords. Block = 64 points (one (b,h) row).

#define DD 64
#define KTOT 1024
#define TK 128          // codewords per chunk
#define TM 64           // points per block
#define NTHREADS 256
#define NCHUNK (KTOT / TK)

#define PSROW 68        // 64 points + 4 pad
#define CSROW 132       // 128 codewords + 4 pad
#define SMEM_FLOATS (DD * PSROW + 2 * DD * CSROW)   // 21248 floats = 84992 B

__device__ float g_cbT[DD * KTOT];   // codebook transposed [d][k]
__device__ float g_cnorm[KTOT];

#define FMA2(d, a, b) \
    asm("fma.rn.f32x2 %0, %1, %2, %0;" : "+l"(d) : "l"(a), "l"(b))
#define UNPACK2(u0, u1, v) \
    asm("mov.b64 {%0, %1}, %2;" : "=r"(u0), "=r"(u1) : "l"(v))
#define DUP2(d, s) \
    asm("mov.b64 %0, {%1, %1};" : "=l"(d) : "r"(s))
#define CP_ASYNC16(dst, src) \
    asm volatile("cp.async.ca.shared.global [%0], [%1], 16;" :: "r"(dst), "l"(src))
#define CP_COMMIT() asm volatile("cp.async.commit_group;" ::: "memory")
#define CP_WAIT(n)  asm volatile("cp.async.wait_group %0;" :: "n"(n) : "memory")

// ---------------- prep: transpose codebook + norms --------------------------
__global__ void __launch_bounds__(NTHREADS)
prep_cb(const float* __restrict__ cb) {
    int k = blockIdx.x * blockDim.x + threadIdx.x;
    if (k >= KTOT) return;
    float s = 0.f;
#pragma unroll
    for (int d4 = 0; d4 < DD; d4 += 4) {
        float4 v = *(const float4*)(cb + (size_t)k * DD + d4);
        s += v.x * v.x + v.y * v.y + v.z * v.z + v.w * v.w;
        g_cbT[(d4 + 0) * KTOT + k] = v.x;
        g_cbT[(d4 + 1) * KTOT + k] = v.y;
        g_cbT[(d4 + 2) * KTOT + k] = v.z;
        g_cbT[(d4 + 3) * KTOT + k] = v.w;
    }
    g_cnorm[k] = s;
}

// ---------------- main fused kernel -----------------------------------------
__global__ void __launch_bounds__(NTHREADS, 2)
vq_kernel(const float* __restrict__ x, const float* __restrict__ cb,
          float* __restrict__ out, int write_idx) {
    extern __shared__ float smem[];
    float* ps  = smem;                       // [DD][PSROW]
    float* cs0 = smem + DD * PSROW;          // [DD][CSROW] buffer 0
    float* cs1 = cs0 + DD * CSROW;           // [DD][CSROW] buffer 1

    const int tid = threadIdx.x;
    const int wid = tid >> 5;          // warp -> points 8*wid .. 8*wid+7
    const int tx  = tid & 31;          // lane -> codewords 4*tx .. 4*tx+3

    const int bh = blockIdx.x;         // 0..1023
    const int b = bh >> 6;
    const int h = bh & 63;
    const float* xbase = x + (size_t)b * (DD * 4096) + (size_t)h * 64;

    // smem u32 addresses for cp.async destinations
    uint32_t sbase;
    asm("{ .reg .u64 t; cvta.to.shared.u64 t, %1; cvt.u32.u64 %0, t; }"
        : "=r"(sbase) : "l"(smem));
    const uint32_t cs_u32[2] = {sbase + (uint32_t)(DD * PSROW) * 4u,
                                sbase + (uint32_t)(DD * PSROW + DD * CSROW) * 4u};
    float* const cs_ptr[2] = {cs0, cs1};

    // This thread's 8 cp.async slots per chunk (d = tid>>5 + 8*r, c4 = (tid&31)*4)
    const int ld_d0 = tid >> 5;        // 0..7
    const int ld_c4 = (tid & 31) * 4;  // 0..124

    // Point tile: straight float4 copy (w contiguous both sides).
    for (int i = tid; i < DD * 16; i += NTHREADS) {
        int d  = i >> 4;
        int w4 = (i & 15) * 4;
        *(float4*)(ps + d * PSROW + w4) =
            *(const float4*)(xbase + (size_t)d * 4096 + w4);
    }

    // Prefetch chunk 0 into buffer 0.
#pragma unroll
    for (int r = 0; r < 8; r++) {
        int d = ld_d0 + 8 * r;
        CP_ASYNC16(cs_u32[0] + (uint32_t)(d * CSROW + ld_c4) * 4u,
                   g_cbT + (size_t)d * KTOT + 0 + ld_c4);
    }
    CP_COMMIT();

    float bestv[8];
    int   besti[8];
#pragma unroll
    for (int p = 0; p < 8; p++) { bestv[p] = 3.4e38f; besti[p] = 0; }

    const float* arow0 = ps + 8 * wid;

    for (int j = 0; j < NCHUNK; j++) {
        const int buf = j & 1;
        // Prefetch next chunk into the other buffer (safe: last computed at j-1,
        // trailing __syncthreads below fenced it).
        if (j + 1 < NCHUNK) {
            const int chunk1 = (j + 1) * TK;
#pragma unroll
            for (int r = 0; r < 8; r++) {
                int d = ld_d0 + 8 * r;
                CP_ASYNC16(cs_u32[buf ^ 1] + (uint32_t)(d * CSROW + ld_c4) * 4u,
                           g_cbT + (size_t)d * KTOT + chunk1 + ld_c4);
            }
            CP_COMMIT();
            CP_WAIT(1);   // current chunk's group (issued last iter) complete
        } else {
            CP_WAIT(0);
        }
        __syncthreads();

        const float* brow0 = cs_ptr[buf] + 4 * tx;

        unsigned long long acc[4][4];
#pragma unroll
        for (int q = 0; q < 4; q++)
#pragma unroll
            for (int jj = 0; jj < 4; jj++) acc[q][jj] = 0ull;

#pragma unroll 4
        for (int d = 0; d < DD; d++) {
            const ulonglong2* ar = (const ulonglong2*)(arow0 + (size_t)d * PSROW);
            ulonglong2 arv0 = ar[0];
            ulonglong2 arv1 = ar[1];
            float4 c = *(const float4*)(brow0 + (size_t)d * CSROW);
            unsigned long long b0, b1, b2, b3;
            DUP2(b0, __float_as_uint(c.x));
            DUP2(b1, __float_as_uint(c.y));
            DUP2(b2, __float_as_uint(c.z));
            DUP2(b3, __float_as_uint(c.w));
            FMA2(acc[0][0], arv0.x, b0); FMA2(acc[0][1], arv0.x, b1);
            FMA2(acc[0][2], arv0.x, b2); FMA2(acc[0][3], arv0.x, b3);
            FMA2(acc[1][0], arv0.y, b0); FMA2(acc[1][1], arv0.y, b1);
            FMA2(acc[1][2], arv0.y, b2); FMA2(acc[1][3], arv0.y, b3);
            FMA2(acc[2][0], arv1.x, b0); FMA2(acc[2][1], arv1.x, b1);
            FMA2(acc[2][2], arv1.x, b2); FMA2(acc[2][3], arv1.x, b3);
            FMA2(acc[3][0], arv1.y, b0); FMA2(acc[3][1], arv1.y, b1);
            FMA2(acc[3][2], arv1.y, b2); FMA2(acc[3][3], arv1.y, b3);
        }

        // d2 = ||c||^2 - 2 x.c ; ascending codeword order + strict < ==
        // first-index tie-break (matches jnp.argmin).
        const int c0 = j * TK + 4 * tx;
        float4 nrm = __ldg((const float4*)(g_cnorm + c0));
        const float nn[4] = {nrm.x, nrm.y, nrm.z, nrm.w};
#pragma unroll
        for (int jj = 0; jj < 4; jj++) {
#pragma unroll
            for (int q = 0; q < 4; q++) {
                uint32_t u0, u1;
                UNPACK2(u0, u1, acc[q][jj]);
                float d2a = fmaf(-2.f, __uint_as_float(u0), nn[jj]);
                float d2b = fmaf(-2.f, __uint_as_float(u1), nn[jj]);
                if (d2a < bestv[2 * q + 0]) { bestv[2 * q + 0] = d2a; besti[2 * q + 0] = c0 + jj; }
                if (d2b < bestv[2 * q + 1]) { bestv[2 * q + 1] = d2b; besti[2 * q + 1] = c0 + jj; }
            }
        }
        __syncthreads();   // all warps done with cs[buf] before it is refilled
    }

    // Warp argmin across lanes (disjoint codeword ranges, same 8 points).
#pragma unroll
    for (int off = 16; off > 0; off >>= 1) {
#pragma unroll
        for (int p = 0; p < 8; p++) {
            float v2 = __shfl_down_sync(0xFFFFFFFFu, bestv[p], off);
            int   c2 = __shfl_down_sync(0xFFFFFFFFu, besti[p], off);
            if (v2 < bestv[p] || (v2 == bestv[p] && c2 < besti[p])) {
                bestv[p] = v2;
                besti[p] = c2;
            }
        }
    }

    __syncthreads();
    int* bidx = (int*)smem;  // 64 ints
    if (tx == 0) {
#pragma unroll
        for (int p = 0; p < 8; p++) bidx[8 * wid + p] = besti[p];
    }
    __syncthreads();

    // Gather winning codebook rows coalesced into smem, then write transposed.
    float* tmp = smem + 128;  // [TM][68] staging
    for (int i = tid; i < TM * 16; i += NTHREADS) {
        int w  = i >> 4;
        int d4 = (i & 15) * 4;
        *(float4*)(tmp + w * 68 + d4) =
            *(const float4*)(cb + (size_t)bidx[w] * DD + d4);
    }
    __syncthreads();
    float* qbase = out + (size_t)b * (DD * 4096) + (size_t)h * 64;
    for (int i = tid; i < TM * 16; i += NTHREADS) {
        int d  = i >> 4;
        int w4 = (i & 15) * 4;
        float4 v;
        v.x = tmp[(w4 + 0) * 68 + d];
        v.y = tmp[(w4 + 1) * 68 + d];
        v.z = tmp[(w4 + 2) * 68 + d];
        v.w = tmp[(w4 + 3) * 68 + d];
        *(float4*)(qbase + (size_t)d * 4096 + w4) = v;
    }

    if (write_idx && tid < TM) {
        out[(size_t)4194304 + (size_t)bh * 64 + tid] = (float)bidx[tid];
    }
}

// ---------------- launch -----------------------------------------------------
extern "C" void kernel_launch(void* const* d_in, const int* in_sizes, int n_in,
                              void* d_out, int out_size) {
    const float* x  = (const float*)d_in[0];
    const float* cb = (const float*)d_in[1];
    if (n_in >= 2 && in_sizes[0] == KTOT * DD && in_sizes[1] == 16 * 64 * 64 * 64) {
        x  = (const float*)d_in[1];
        cb = (const float*)d_in[0];
    }
    float* out = (float*)d_out;

    const int smem_bytes = SMEM_FLOATS * (int)sizeof(float);
    cudaFuncSetAttribute(vq_kernel, cudaFuncAttributeMaxDynamicSharedMemorySize,
                         smem_bytes);

    int write_idx = (out_size >= 4194304 + 65536) ? 1 : 0;
    prep_cb<<<(KTOT + NTHREADS - 1) / NTHREADS, NTHREADS>>>(cb);
    vq_kernel<<<1024, NTHREADS, smem_bytes>>>(x, cb, out, write_idx);
}